// round 1
// baseline (speedup 1.0000x reference)
#include <cuda_runtime.h>
#include <cuda_bf16.h>

#define N_USER 50000
#define N_ITEM 100000
#define N_TOT  150000
#define D      64
#define NNZ    2400000
#define B_SZ   4096
#define N_LAYERS 3

// Scratch (device globals: allocation-free rule)
__device__ float g_ego[N_TOT * D];        // current layer embeddings (unnormalized)
__device__ float g_L[N_TOT * D];          // SPMM accumulator
__device__ float g_all[N_TOT * 4 * D];    // concat of [ego0 | norm1 | norm2 | norm3]

// ---------------------------------------------------------------------------
// init: g_ego = concat(user_emb, item_emb); g_all[:, 0:64] = same; g_L = 0
// ---------------------------------------------------------------------------
__global__ void init_kernel(const float* __restrict__ user_emb,
                            const float* __restrict__ item_emb) {
    int i = blockIdx.x * blockDim.x + threadIdx.x;
    if (i >= N_TOT * D) return;
    float v = (i < N_USER * D) ? user_emb[i] : item_emb[i - N_USER * D];
    g_ego[i] = v;
    int row = i >> 6, col = i & 63;
    g_all[row * (4 * D) + col] = v;
    g_L[i] = 0.0f;
}

// ---------------------------------------------------------------------------
// SPMM: g_L[rows[nz]] += vals[nz] * g_ego[cols[nz]]   (vector f32x4 reductions)
// 16 threads per nnz, each handles a float4 chunk of the 64-wide row.
// ---------------------------------------------------------------------------
__global__ void spmm_kernel(const float* __restrict__ vals,
                            const int*   __restrict__ rows,
                            const int*   __restrict__ cols) {
    int idx = blockIdx.x * blockDim.x + threadIdx.x;   // NNZ*16 threads
    if (idx >= NNZ * 16) return;
    int nz = idx >> 4;
    int c  = (idx & 15) << 2;
    float v = vals[nz];
    int r = rows[nz];
    int cl = cols[nz];
    float4 e = *reinterpret_cast<const float4*>(&g_ego[cl * D + c]);
    float4 p;
    p.x = v * e.x; p.y = v * e.y; p.z = v * e.z; p.w = v * e.w;
    float* dst = &g_L[r * D + c];
    asm volatile("red.global.add.v4.f32 [%0], {%1, %2, %3, %4};"
                 :: "l"(dst), "f"(p.x), "f"(p.y), "f"(p.z), "f"(p.w)
                 : "memory");
}

// ---------------------------------------------------------------------------
// Fused layer: LI = L+E, BI = L*E;
//   out = leaky_relu(LI@Wgc + BI@Wbi + 2*b, 0.01)
//   g_ego = out;  g_all[:, (layer+1)*64 : ] = out / max(||out||, 1e-12)
//   Also zeroes g_L (ready for next layer's SPMM).
// One warp per row; lane handles columns (2*lane, 2*lane+1); W in shared.
// ---------------------------------------------------------------------------
__global__ void layer_kernel(const float* __restrict__ Wgc,
                             const float* __restrict__ Wbi,
                             const float* __restrict__ bb,
                             int layer) {
    __shared__ float sWgc[D * D];
    __shared__ float sWbi[D * D];
    __shared__ float sLi[8][D];
    __shared__ float sBi[8][D];

    int tid = threadIdx.x;
    for (int i = tid; i < D * D; i += 256) {
        sWgc[i] = Wgc[i];
        sWbi[i] = Wbi[i];
    }
    __syncthreads();

    int warp = tid >> 5, lane = tid & 31;
    float2 b2 = *reinterpret_cast<const float2*>(&bb[2 * lane]);

    int rowBase = blockIdx.x * 32;   // 32 rows per block, 8 warps x 4 iters
    #pragma unroll
    for (int rr = 0; rr < 4; rr++) {
        int row = rowBase + rr * 8 + warp;
        if (row < N_TOT) {
            float2 l2 = *reinterpret_cast<const float2*>(&g_L[row * D + 2 * lane]);
            float2 e2 = *reinterpret_cast<const float2*>(&g_ego[row * D + 2 * lane]);
            sLi[warp][2 * lane]     = l2.x + e2.x;
            sLi[warp][2 * lane + 1] = l2.y + e2.y;
            sBi[warp][2 * lane]     = l2.x * e2.x;
            sBi[warp][2 * lane + 1] = l2.y * e2.y;
            // zero accumulator for next layer's SPMM
            *reinterpret_cast<float2*>(&g_L[row * D + 2 * lane]) = make_float2(0.f, 0.f);
            __syncwarp();

            float2 acc = make_float2(0.f, 0.f);
            #pragma unroll
            for (int d = 0; d < D; d++) {
                float li = sLi[warp][d];
                float bi = sBi[warp][d];
                float2 wg = *reinterpret_cast<const float2*>(&sWgc[d * D + 2 * lane]);
                float2 wb = *reinterpret_cast<const float2*>(&sWbi[d * D + 2 * lane]);
                acc.x += li * wg.x + bi * wb.x;
                acc.y += li * wg.y + bi * wb.y;
            }
            // NOTE: b_bi added to BOTH branches in the reference -> 2*b
            acc.x += 2.0f * b2.x;
            acc.y += 2.0f * b2.y;
            float x = acc.x > 0.f ? acc.x : 0.01f * acc.x;
            float y = acc.y > 0.f ? acc.y : 0.01f * acc.y;

            float ss = x * x + y * y;
            #pragma unroll
            for (int o = 16; o; o >>= 1)
                ss += __shfl_xor_sync(0xffffffffu, ss, o);
            float inv = 1.0f / fmaxf(sqrtf(ss), 1e-12f);

            *reinterpret_cast<float2*>(&g_ego[row * D + 2 * lane]) = make_float2(x, y);
            *reinterpret_cast<float2*>(
                &g_all[row * (4 * D) + (layer + 1) * D + 2 * lane]) =
                make_float2(x * inv, y * inv);
        }
        __syncwarp();
    }
}

// ---------------------------------------------------------------------------
// Final gather: out = [ all_embs[users] | all_embs[n_user+pos] | all_embs[n_user+neg] ]
// ---------------------------------------------------------------------------
__global__ void gather_kernel(const int* __restrict__ users,
                              const int* __restrict__ pos_items,
                              const int* __restrict__ neg_items,
                              float* __restrict__ out) {
    int idx = blockIdx.x * blockDim.x + threadIdx.x;  // 3*B*256
    if (idx >= 3 * B_SZ * (4 * D)) return;
    int which = idx / (B_SZ * 4 * D);
    int rem   = idx - which * (B_SZ * 4 * D);
    int b = rem >> 8;          // / 256
    int c = rem & 255;
    int row;
    if (which == 0)      row = users[b];
    else if (which == 1) row = N_USER + pos_items[b];
    else                 row = N_USER + neg_items[b];
    out[idx] = g_all[row * (4 * D) + c];
}

// ---------------------------------------------------------------------------
extern "C" void kernel_launch(void* const* d_in, const int* in_sizes, int n_in,
                              void* d_out, int out_size) {
    const float* user_emb  = (const float*)d_in[0];
    const float* item_emb  = (const float*)d_in[1];
    const float* W_gc      = (const float*)d_in[2];   // [3,64,64]
    const float* W_bi      = (const float*)d_in[3];   // [3,64,64]
    const float* b_bi      = (const float*)d_in[4];   // [3,1,64]
    const float* vals      = (const float*)d_in[5];
    const int*   rows      = (const int*)d_in[6];
    const int*   cols      = (const int*)d_in[7];
    const int*   users     = (const int*)d_in[8];
    const int*   pos_items = (const int*)d_in[9];
    const int*   neg_items = (const int*)d_in[10];
    float* out = (float*)d_out;

    {
        int total = N_TOT * D;
        init_kernel<<<(total + 255) / 256, 256>>>(user_emb, item_emb);
    }

    for (int k = 0; k < N_LAYERS; k++) {
        {
            int total = NNZ * 16;
            spmm_kernel<<<(total + 255) / 256, 256>>>(vals, rows, cols);
        }
        {
            int blocks = (N_TOT + 31) / 32;
            layer_kernel<<<blocks, 256>>>(W_gc + k * D * D,
                                          W_bi + k * D * D,
                                          b_bi + k * D, k);
        }
    }

    {
        int total = 3 * B_SZ * 4 * D;
        gather_kernel<<<(total + 255) / 256, 256>>>(users, pos_items, neg_items, out);
    }
}

// round 2
// speedup vs baseline: 1.9241x; 1.9241x over previous
#include <cuda_runtime.h>
#include <cuda_bf16.h>

#define N_USER 50000
#define N_ITEM 100000
#define N_TOT  150000
#define D      64
#define NNZ    2400000
#define B_SZ   4096
#define N_LAYERS 3

#define SCAN_B 1024
#define SCAN_NBLK ((N_TOT + SCAN_B - 1) / SCAN_B)   // 147

// ---------------- device scratch (allocation-free rule) ----------------
__device__ float g_ego[N_TOT * D];        // current embeddings (unnormalized)
__device__ float g_L[N_TOT * D];          // SPMM output
__device__ float g_all[N_TOT * 4 * D];    // [ego0 | norm1 | norm2 | norm3]
__device__ int   g_cnt[N_TOT];            // per-row nnz counts
__device__ int   g_rowptr[N_TOT + 1];     // CSR row pointers
__device__ int   g_cur[N_TOT];            // scatter cursors
__device__ int   g_bsum[SCAN_NBLK + 1];   // scan partials
__device__ int2  g_csr[NNZ];              // packed (col, val-bits)

// ---------------------------------------------------------------------------
// init: g_ego = concat(user,item); g_all[:,0:64] = same; zero g_cnt
// ---------------------------------------------------------------------------
__global__ void init_kernel(const float* __restrict__ user_emb,
                            const float* __restrict__ item_emb) {
    int i = blockIdx.x * blockDim.x + threadIdx.x;
    if (i >= N_TOT * D) return;
    float v = (i < N_USER * D) ? user_emb[i] : item_emb[i - N_USER * D];
    g_ego[i] = v;
    int row = i >> 6, col = i & 63;
    g_all[row * (4 * D) + col] = v;
    if (col == 0) g_cnt[row] = 0;
}

// ---------------------------------------------------------------------------
// CSR build: histogram -> scan (3 kernels) -> scatter
// ---------------------------------------------------------------------------
__global__ void hist_kernel(const int* __restrict__ rows) {
    int i = blockIdx.x * blockDim.x + threadIdx.x;
    if (i < NNZ) atomicAdd(&g_cnt[rows[i]], 1);
}

__global__ void scan1_kernel() {
    __shared__ int s[SCAN_B];
    int tid = threadIdx.x;
    int gid = blockIdx.x * SCAN_B + tid;
    int v = (gid < N_TOT) ? g_cnt[gid] : 0;
    s[tid] = v;
    __syncthreads();
    #pragma unroll
    for (int off = 1; off < SCAN_B; off <<= 1) {
        int t = (tid >= off) ? s[tid - off] : 0;
        __syncthreads();
        s[tid] += t;
        __syncthreads();
    }
    if (gid < N_TOT) g_rowptr[gid] = s[tid] - v;   // exclusive within block
    if (tid == SCAN_B - 1) g_bsum[blockIdx.x] = s[tid];
}

__global__ void scan2_kernel() {
    __shared__ int s[256];
    int tid = threadIdx.x;   // 256 >= SCAN_NBLK
    int v = (tid < SCAN_NBLK) ? g_bsum[tid] : 0;
    s[tid] = v;
    __syncthreads();
    #pragma unroll
    for (int off = 1; off < 256; off <<= 1) {
        int t = (tid >= off) ? s[tid - off] : 0;
        __syncthreads();
        s[tid] += t;
        __syncthreads();
    }
    if (tid < SCAN_NBLK) g_bsum[tid] = s[tid] - v; // exclusive block offsets
}

__global__ void scan3_kernel() {
    int gid = blockIdx.x * SCAN_B + threadIdx.x;
    if (gid < N_TOT) {
        g_rowptr[gid] += g_bsum[blockIdx.x];
        g_cur[gid] = 0;
    }
    if (gid == 0) g_rowptr[N_TOT] = NNZ;
}

__global__ void scatter_kernel(const float* __restrict__ vals,
                               const int*   __restrict__ rows,
                               const int*   __restrict__ cols) {
    int i = blockIdx.x * blockDim.x + threadIdx.x;
    if (i >= NNZ) return;
    int r = rows[i];
    int pos = g_rowptr[r] + atomicAdd(&g_cur[r], 1);
    g_csr[pos] = make_int2(cols[i], __float_as_int(vals[i]));
}

// ---------------------------------------------------------------------------
// CSR SPMM: g_L[row] = sum_j val_j * g_ego[col_j]; 16 threads per row,
// register accumulation, single store (no atomics, no pre-zero).
// ---------------------------------------------------------------------------
__global__ void spmm_csr_kernel() {
    int tid = threadIdx.x;
    int row = blockIdx.x * 16 + (tid >> 4);     // grid = N_TOT/16 exactly
    int c   = (tid & 15) << 2;
    int s0 = g_rowptr[row];
    int e0 = g_rowptr[row + 1];
    float4 acc = make_float4(0.f, 0.f, 0.f, 0.f);
    int j = s0;
    for (; j + 2 <= e0; j += 2) {
        int2 a = g_csr[j];
        int2 b = g_csr[j + 1];
        float4 va = __ldg((const float4*)&g_ego[a.x * D + c]);
        float4 vb = __ldg((const float4*)&g_ego[b.x * D + c]);
        float fa = __int_as_float(a.y);
        float fb = __int_as_float(b.y);
        acc.x += fa * va.x + fb * vb.x;
        acc.y += fa * va.y + fb * vb.y;
        acc.z += fa * va.z + fb * vb.z;
        acc.w += fa * va.w + fb * vb.w;
    }
    if (j < e0) {
        int2 a = g_csr[j];
        float4 va = __ldg((const float4*)&g_ego[a.x * D + c]);
        float fa = __int_as_float(a.y);
        acc.x += fa * va.x; acc.y += fa * va.y;
        acc.z += fa * va.z; acc.w += fa * va.w;
    }
    *reinterpret_cast<float4*>(&g_L[row * D + c]) = acc;
}

// ---------------------------------------------------------------------------
// Fused layer as one GEMM:  A' = [L+E | L*E]  (Mx128),  W' = [Wgc; Wbi] (128x64)
//   out = leaky_relu(A'@W' + 2*b);  g_ego = out;  g_all[:,(k+1)*64:] = normalize(out)
// 256 threads, 32 rows x 64 cols per block; thread computes 2x4 tile.
// ---------------------------------------------------------------------------
__global__ void layer_kernel(const float* __restrict__ Wgc,
                             const float* __restrict__ Wbi,
                             const float* __restrict__ bb,
                             int layer) {
    __shared__ float sA[32 * 128];   // sA[row][k]
    __shared__ float sW[128 * 64];   // sW[k][n]

    int tid = threadIdx.x;

    // stage W' (8192 floats)
    {
        const float4* wg4 = (const float4*)Wgc;
        const float4* wb4 = (const float4*)Wbi;
        float4* sW4 = (float4*)sW;
        #pragma unroll
        for (int i = 0; i < 4; i++) sW4[tid + i * 256] = wg4[tid + i * 256];
        #pragma unroll
        for (int i = 0; i < 4; i++) sW4[1024 + tid + i * 256] = wb4[tid + i * 256];
    }

    // stage A': 32 rows, thread handles row=tid>>3, 8 cols starting (tid&7)*8
    int rowBase = blockIdx.x * 32;
    {
        int r = tid >> 3;
        int seg = (tid & 7) * 8;
        int grow = rowBase + r;
        float4 l0, l1, e0, e1;
        if (grow < N_TOT) {
            l0 = *(const float4*)&g_L[grow * D + seg];
            l1 = *(const float4*)&g_L[grow * D + seg + 4];
            e0 = *(const float4*)&g_ego[grow * D + seg];
            e1 = *(const float4*)&g_ego[grow * D + seg + 4];
        } else {
            l0 = l1 = e0 = e1 = make_float4(0.f, 0.f, 0.f, 0.f);
        }
        float4 li0 = make_float4(l0.x + e0.x, l0.y + e0.y, l0.z + e0.z, l0.w + e0.w);
        float4 li1 = make_float4(l1.x + e1.x, l1.y + e1.y, l1.z + e1.z, l1.w + e1.w);
        float4 bi0 = make_float4(l0.x * e0.x, l0.y * e0.y, l0.z * e0.z, l0.w * e0.w);
        float4 bi1 = make_float4(l1.x * e1.x, l1.y * e1.y, l1.z * e1.z, l1.w * e1.w);
        *(float4*)&sA[r * 128 + seg]           = li0;
        *(float4*)&sA[r * 128 + seg + 4]       = li1;
        *(float4*)&sA[r * 128 + 64 + seg]      = bi0;
        *(float4*)&sA[r * 128 + 64 + seg + 4]  = bi1;
    }
    __syncthreads();

    int ty = tid >> 4;       // 0..15 -> rows 2ty, 2ty+1
    int tx = tid & 15;       // cols 4tx..4tx+3
    const float* pa0 = &sA[(2 * ty) * 128];
    const float* pa1 = &sA[(2 * ty + 1) * 128];

    float acc00 = 0.f, acc01 = 0.f, acc02 = 0.f, acc03 = 0.f;
    float acc10 = 0.f, acc11 = 0.f, acc12 = 0.f, acc13 = 0.f;

    #pragma unroll 16
    for (int k = 0; k < 128; k++) {
        float a0 = pa0[k];
        float a1 = pa1[k];
        float4 w = *(const float4*)&sW[k * 64 + 4 * tx];
        acc00 += a0 * w.x; acc01 += a0 * w.y; acc02 += a0 * w.z; acc03 += a0 * w.w;
        acc10 += a1 * w.x; acc11 += a1 * w.y; acc12 += a1 * w.z; acc13 += a1 * w.w;
    }

    float4 b4 = *(const float4*)&bb[4 * tx];   // reference adds b to BOTH branches
    float x0 = acc00 + 2.f * b4.x, x1 = acc01 + 2.f * b4.y;
    float x2 = acc02 + 2.f * b4.z, x3 = acc03 + 2.f * b4.w;
    float y0 = acc10 + 2.f * b4.x, y1 = acc11 + 2.f * b4.y;
    float y2 = acc12 + 2.f * b4.z, y3 = acc13 + 2.f * b4.w;

    x0 = x0 > 0.f ? x0 : 0.01f * x0;  x1 = x1 > 0.f ? x1 : 0.01f * x1;
    x2 = x2 > 0.f ? x2 : 0.01f * x2;  x3 = x3 > 0.f ? x3 : 0.01f * x3;
    y0 = y0 > 0.f ? y0 : 0.01f * y0;  y1 = y1 > 0.f ? y1 : 0.01f * y1;
    y2 = y2 > 0.f ? y2 : 0.01f * y2;  y3 = y3 > 0.f ? y3 : 0.01f * y3;

    // row norms: reduce across the 16 tx lanes (contiguous half-warp group)
    float ss0 = x0 * x0 + x1 * x1 + x2 * x2 + x3 * x3;
    float ss1 = y0 * y0 + y1 * y1 + y2 * y2 + y3 * y3;
    #pragma unroll
    for (int o = 8; o; o >>= 1) {
        ss0 += __shfl_xor_sync(0xffffffffu, ss0, o);
        ss1 += __shfl_xor_sync(0xffffffffu, ss1, o);
    }
    float inv0 = 1.0f / fmaxf(sqrtf(ss0), 1e-12f);
    float inv1 = 1.0f / fmaxf(sqrtf(ss1), 1e-12f);

    int r0 = rowBase + 2 * ty;
    int r1 = r0 + 1;
    int co = (layer + 1) * D + 4 * tx;
    if (r0 < N_TOT) {
        *(float4*)&g_ego[r0 * D + 4 * tx] = make_float4(x0, x1, x2, x3);
        *(float4*)&g_all[r0 * (4 * D) + co] =
            make_float4(x0 * inv0, x1 * inv0, x2 * inv0, x3 * inv0);
    }
    if (r1 < N_TOT) {
        *(float4*)&g_ego[r1 * D + 4 * tx] = make_float4(y0, y1, y2, y3);
        *(float4*)&g_all[r1 * (4 * D) + co] =
            make_float4(y0 * inv1, y1 * inv1, y2 * inv1, y3 * inv1);
    }
}

// ---------------------------------------------------------------------------
// Final gather
// ---------------------------------------------------------------------------
__global__ void gather_kernel(const int* __restrict__ users,
                              const int* __restrict__ pos_items,
                              const int* __restrict__ neg_items,
                              float* __restrict__ out) {
    int idx = blockIdx.x * blockDim.x + threadIdx.x;  // 3*B*256
    if (idx >= 3 * B_SZ * (4 * D)) return;
    int which = idx / (B_SZ * 4 * D);
    int rem   = idx - which * (B_SZ * 4 * D);
    int b = rem >> 8;
    int c = rem & 255;
    int row;
    if (which == 0)      row = users[b];
    else if (which == 1) row = N_USER + pos_items[b];
    else                 row = N_USER + neg_items[b];
    out[idx] = g_all[row * (4 * D) + c];
}

// ---------------------------------------------------------------------------
extern "C" void kernel_launch(void* const* d_in, const int* in_sizes, int n_in,
                              void* d_out, int out_size) {
    const float* user_emb  = (const float*)d_in[0];
    const float* item_emb  = (const float*)d_in[1];
    const float* W_gc      = (const float*)d_in[2];
    const float* W_bi      = (const float*)d_in[3];
    const float* b_bi      = (const float*)d_in[4];
    const float* vals      = (const float*)d_in[5];
    const int*   rows      = (const int*)d_in[6];
    const int*   cols      = (const int*)d_in[7];
    const int*   users     = (const int*)d_in[8];
    const int*   pos_items = (const int*)d_in[9];
    const int*   neg_items = (const int*)d_in[10];
    float* out = (float*)d_out;

    init_kernel<<<(N_TOT * D + 255) / 256, 256>>>(user_emb, item_emb);

    hist_kernel<<<(NNZ + 255) / 256, 256>>>(rows);
    scan1_kernel<<<SCAN_NBLK, SCAN_B>>>();
    scan2_kernel<<<1, 256>>>();
    scan3_kernel<<<SCAN_NBLK, SCAN_B>>>();
    scatter_kernel<<<(NNZ + 255) / 256, 256>>>(vals, rows, cols);

    for (int k = 0; k < N_LAYERS; k++) {
        spmm_csr_kernel<<<N_TOT / 16, 256>>>();
        layer_kernel<<<(N_TOT + 31) / 32, 256>>>(W_gc + k * D * D,
                                                 W_bi + k * D * D,
                                                 b_bi + k * D, k);
    }

    gather_kernel<<<(3 * B_SZ * 4 * D + 255) / 256, 256>>>(users, pos_items,
                                                           neg_items, out);
}

// round 3
// speedup vs baseline: 2.0390x; 1.0597x over previous
#include <cuda_runtime.h>
#include <cuda_bf16.h>

#define N_USER 50000
#define N_ITEM 100000
#define N_TOT  150000
#define D      64
#define NNZ    2400000
#define B_SZ   4096
#define N_LAYERS 3

#define SCAN_B 1024
#define SCAN_NBLK ((N_TOT + SCAN_B - 1) / SCAN_B)   // 147

#define LBLK ((N_TOT + 31) / 32)                    // 4688 layer blocks

// ---------------- device scratch (allocation-free rule) ----------------
__device__ float g_E0[N_TOT * D];         // ego ping
__device__ float g_E1[N_TOT * D];         // ego pong
__device__ float g_all[N_TOT * 4 * D];    // [ego0 | norm1 | norm2 | norm3]
__device__ int   g_cnt[N_TOT];
__device__ int   g_rowptr[N_TOT + 1];
__device__ int   g_cur[N_TOT];
__device__ int   g_bsum[SCAN_NBLK + 1];
__device__ int2  g_csr[NNZ];              // packed (col, val-bits)

// ---------------------------------------------------------------------------
__global__ void init_kernel(const float* __restrict__ user_emb,
                            const float* __restrict__ item_emb) {
    int i = blockIdx.x * blockDim.x + threadIdx.x;
    if (i >= N_TOT * D) return;
    float v = (i < N_USER * D) ? user_emb[i] : item_emb[i - N_USER * D];
    g_E0[i] = v;
    int row = i >> 6, col = i & 63;
    g_all[row * (4 * D) + col] = v;
    if (col == 0) g_cnt[row] = 0;
}

// ---------------------------------------------------------------------------
// CSR build
// ---------------------------------------------------------------------------
__global__ void hist_kernel(const int* __restrict__ rows) {
    int i = blockIdx.x * blockDim.x + threadIdx.x;
    if (i < NNZ) atomicAdd(&g_cnt[rows[i]], 1);
}

__global__ void scan1_kernel() {
    __shared__ int s[SCAN_B];
    int tid = threadIdx.x;
    int gid = blockIdx.x * SCAN_B + tid;
    int v = (gid < N_TOT) ? g_cnt[gid] : 0;
    s[tid] = v;
    __syncthreads();
    #pragma unroll
    for (int off = 1; off < SCAN_B; off <<= 1) {
        int t = (tid >= off) ? s[tid - off] : 0;
        __syncthreads();
        s[tid] += t;
        __syncthreads();
    }
    if (gid < N_TOT) g_rowptr[gid] = s[tid] - v;
    if (tid == SCAN_B - 1) g_bsum[blockIdx.x] = s[tid];
}

__global__ void scan2_kernel() {
    __shared__ int s[256];
    int tid = threadIdx.x;
    int v = (tid < SCAN_NBLK) ? g_bsum[tid] : 0;
    s[tid] = v;
    __syncthreads();
    #pragma unroll
    for (int off = 1; off < 256; off <<= 1) {
        int t = (tid >= off) ? s[tid - off] : 0;
        __syncthreads();
        s[tid] += t;
        __syncthreads();
    }
    if (tid < SCAN_NBLK) g_bsum[tid] = s[tid] - v;
}

__global__ void scan3_kernel() {
    int gid = blockIdx.x * SCAN_B + threadIdx.x;
    if (gid < N_TOT) {
        g_rowptr[gid] += g_bsum[blockIdx.x];
        g_cur[gid] = 0;
    }
    if (gid == 0) g_rowptr[N_TOT] = NNZ;
}

__global__ void scatter_kernel(const float* __restrict__ vals,
                               const int*   __restrict__ rows,
                               const int*   __restrict__ cols) {
    int i = blockIdx.x * blockDim.x + threadIdx.x;
    if (i >= NNZ) return;
    int r = rows[i];
    int pos = g_rowptr[r] + atomicAdd(&g_cur[r], 1);
    g_csr[pos] = make_int2(cols[i], __float_as_int(vals[i]));
}

// ---------------------------------------------------------------------------
// FUSED layer: per block (32 rows):
//   Phase 1: CSR SPMM into registers (16 thr/row, float4/thr), build
//            sA = [L+E | L*E] (32x128) in shared; stage sW = [Wgc;Wbi].
//   Phase 2: GEMM (2x4 tile/thread), epilogue: +2b, leaky-relu, row-norm,
//            write ego_out and g_all[:, (layer+1)*64 :].
// Blocks at different phases overlap LTS-bound gather with FFMA-bound GEMM.
// ---------------------------------------------------------------------------
__global__ void __launch_bounds__(256)
fused_layer_kernel(const float* __restrict__ ego_in,
                   float*       __restrict__ ego_out,
                   const float* __restrict__ Wgc,
                   const float* __restrict__ Wbi,
                   const float* __restrict__ bb,
                   int layer) {
    __shared__ float sA[32 * 128];   // [row][k]  (LI | BI)
    __shared__ float sW[128 * 64];   // [k][n]    (Wgc ; Wbi)

    int tid = threadIdx.x;
    int rowBase = blockIdx.x * 32;

    // stage W' (no sync needed before phase 1 writes — disjoint smem)
    {
        const float4* wg4 = (const float4*)Wgc;
        const float4* wb4 = (const float4*)Wbi;
        float4* sW4 = (float4*)sW;
        #pragma unroll
        for (int i = 0; i < 4; i++) sW4[tid + i * 256] = wg4[tid + i * 256];
        #pragma unroll
        for (int i = 0; i < 4; i++) sW4[1024 + tid + i * 256] = wb4[tid + i * 256];
    }

    // Phase 1: SPMM 32 rows, 16 threads/row, 2 iterations
    {
        int rsub = tid >> 4;            // 0..15
        int c    = (tid & 15) << 2;     // float4 column offset
        #pragma unroll
        for (int iter = 0; iter < 2; iter++) {
            int rl  = iter * 16 + rsub;        // local row 0..31
            int row = rowBase + rl;
            float4 acc = make_float4(0.f, 0.f, 0.f, 0.f);
            float4 e   = make_float4(0.f, 0.f, 0.f, 0.f);
            if (row < N_TOT) {
                int s0 = g_rowptr[row];
                int e0 = g_rowptr[row + 1];
                int j = s0;
                for (; j + 2 <= e0; j += 2) {
                    int2 a = g_csr[j];
                    int2 b = g_csr[j + 1];
                    float4 va = __ldg((const float4*)&ego_in[a.x * D + c]);
                    float4 vb = __ldg((const float4*)&ego_in[b.x * D + c]);
                    float fa = __int_as_float(a.y);
                    float fb = __int_as_float(b.y);
                    acc.x += fa * va.x + fb * vb.x;
                    acc.y += fa * va.y + fb * vb.y;
                    acc.z += fa * va.z + fb * vb.z;
                    acc.w += fa * va.w + fb * vb.w;
                }
                if (j < e0) {
                    int2 a = g_csr[j];
                    float4 va = __ldg((const float4*)&ego_in[a.x * D + c]);
                    float fa = __int_as_float(a.y);
                    acc.x += fa * va.x; acc.y += fa * va.y;
                    acc.z += fa * va.z; acc.w += fa * va.w;
                }
                e = *(const float4*)&ego_in[row * D + c];
            }
            *(float4*)&sA[rl * 128 + c] =
                make_float4(acc.x + e.x, acc.y + e.y, acc.z + e.z, acc.w + e.w);
            *(float4*)&sA[rl * 128 + 64 + c] =
                make_float4(acc.x * e.x, acc.y * e.y, acc.z * e.z, acc.w * e.w);
        }
    }
    __syncthreads();

    // Phase 2: GEMM, 2 rows x 4 cols per thread
    int ty = tid >> 4;       // 0..15 -> rows 2ty, 2ty+1
    int tx = tid & 15;       // cols 4tx..4tx+3
    const float* pa0 = &sA[(2 * ty) * 128];
    const float* pa1 = pa0 + 128;

    float acc00 = 0.f, acc01 = 0.f, acc02 = 0.f, acc03 = 0.f;
    float acc10 = 0.f, acc11 = 0.f, acc12 = 0.f, acc13 = 0.f;

    #pragma unroll
    for (int k4 = 0; k4 < 32; k4++) {
        float4 A0 = *(const float4*)&pa0[k4 * 4];
        float4 A1 = *(const float4*)&pa1[k4 * 4];
        const float* wp = &sW[(k4 * 4) * 64 + 4 * tx];
        float4 w0 = *(const float4*)(wp);
        float4 w1 = *(const float4*)(wp + 64);
        float4 w2 = *(const float4*)(wp + 128);
        float4 w3 = *(const float4*)(wp + 192);
        acc00 += A0.x * w0.x; acc01 += A0.x * w0.y; acc02 += A0.x * w0.z; acc03 += A0.x * w0.w;
        acc10 += A1.x * w0.x; acc11 += A1.x * w0.y; acc12 += A1.x * w0.z; acc13 += A1.x * w0.w;
        acc00 += A0.y * w1.x; acc01 += A0.y * w1.y; acc02 += A0.y * w1.z; acc03 += A0.y * w1.w;
        acc10 += A1.y * w1.x; acc11 += A1.y * w1.y; acc12 += A1.y * w1.z; acc13 += A1.y * w1.w;
        acc00 += A0.z * w2.x; acc01 += A0.z * w2.y; acc02 += A0.z * w2.z; acc03 += A0.z * w2.w;
        acc10 += A1.z * w2.x; acc11 += A1.z * w2.y; acc12 += A1.z * w2.z; acc13 += A1.z * w2.w;
        acc00 += A0.w * w3.x; acc01 += A0.w * w3.y; acc02 += A0.w * w3.z; acc03 += A0.w * w3.w;
        acc10 += A1.w * w3.x; acc11 += A1.w * w3.y; acc12 += A1.w * w3.z; acc13 += A1.w * w3.w;
    }

    float4 b4 = *(const float4*)&bb[4 * tx];   // reference adds b to BOTH branches
    float x0 = acc00 + 2.f * b4.x, x1 = acc01 + 2.f * b4.y;
    float x2 = acc02 + 2.f * b4.z, x3 = acc03 + 2.f * b4.w;
    float y0 = acc10 + 2.f * b4.x, y1 = acc11 + 2.f * b4.y;
    float y2 = acc12 + 2.f * b4.z, y3 = acc13 + 2.f * b4.w;

    x0 = x0 > 0.f ? x0 : 0.01f * x0;  x1 = x1 > 0.f ? x1 : 0.01f * x1;
    x2 = x2 > 0.f ? x2 : 0.01f * x2;  x3 = x3 > 0.f ? x3 : 0.01f * x3;
    y0 = y0 > 0.f ? y0 : 0.01f * y0;  y1 = y1 > 0.f ? y1 : 0.01f * y1;
    y2 = y2 > 0.f ? y2 : 0.01f * y2;  y3 = y3 > 0.f ? y3 : 0.01f * y3;

    float ss0 = x0 * x0 + x1 * x1 + x2 * x2 + x3 * x3;
    float ss1 = y0 * y0 + y1 * y1 + y2 * y2 + y3 * y3;
    #pragma unroll
    for (int o = 8; o; o >>= 1) {
        ss0 += __shfl_xor_sync(0xffffffffu, ss0, o);
        ss1 += __shfl_xor_sync(0xffffffffu, ss1, o);
    }
    float inv0 = 1.0f / fmaxf(sqrtf(ss0), 1e-12f);
    float inv1 = 1.0f / fmaxf(sqrtf(ss1), 1e-12f);

    int r0 = rowBase + 2 * ty;
    int r1 = r0 + 1;
    int co = (layer + 1) * D + 4 * tx;
    if (r0 < N_TOT) {
        *(float4*)&ego_out[r0 * D + 4 * tx] = make_float4(x0, x1, x2, x3);
        *(float4*)&g_all[r0 * (4 * D) + co] =
            make_float4(x0 * inv0, x1 * inv0, x2 * inv0, x3 * inv0);
    }
    if (r1 < N_TOT) {
        *(float4*)&ego_out[r1 * D + 4 * tx] = make_float4(y0, y1, y2, y3);
        *(float4*)&g_all[r1 * (4 * D) + co] =
            make_float4(y0 * inv1, y1 * inv1, y2 * inv1, y3 * inv1);
    }
}

// ---------------------------------------------------------------------------
__global__ void gather_kernel(const int* __restrict__ users,
                              const int* __restrict__ pos_items,
                              const int* __restrict__ neg_items,
                              float* __restrict__ out) {
    int idx = blockIdx.x * blockDim.x + threadIdx.x;  // 3*B*256
    if (idx >= 3 * B_SZ * (4 * D)) return;
    int which = idx / (B_SZ * 4 * D);
    int rem   = idx - which * (B_SZ * 4 * D);
    int b = rem >> 8;
    int c = rem & 255;
    int row;
    if (which == 0)      row = users[b];
    else if (which == 1) row = N_USER + pos_items[b];
    else                 row = N_USER + neg_items[b];
    out[idx] = g_all[row * (4 * D) + c];
}

// ---------------------------------------------------------------------------
extern "C" void kernel_launch(void* const* d_in, const int* in_sizes, int n_in,
                              void* d_out, int out_size) {
    const float* user_emb  = (const float*)d_in[0];
    const float* item_emb  = (const float*)d_in[1];
    const float* W_gc      = (const float*)d_in[2];
    const float* W_bi      = (const float*)d_in[3];
    const float* b_bi      = (const float*)d_in[4];
    const float* vals      = (const float*)d_in[5];
    const int*   rows      = (const int*)d_in[6];
    const int*   cols      = (const int*)d_in[7];
    const int*   users     = (const int*)d_in[8];
    const int*   pos_items = (const int*)d_in[9];
    const int*   neg_items = (const int*)d_in[10];
    float* out = (float*)d_out;

    init_kernel<<<(N_TOT * D + 255) / 256, 256>>>(user_emb, item_emb);

    hist_kernel<<<(NNZ + 255) / 256, 256>>>(rows);
    scan1_kernel<<<SCAN_NBLK, SCAN_B>>>();
    scan2_kernel<<<1, 256>>>();
    scan3_kernel<<<SCAN_NBLK, SCAN_B>>>();
    scatter_kernel<<<(NNZ + 255) / 256, 256>>>(vals, rows, cols);

    float* e0; float* e1;
    cudaGetSymbolAddress((void**)&e0, g_E0);
    cudaGetSymbolAddress((void**)&e1, g_E1);

    for (int k = 0; k < N_LAYERS; k++) {
        const float* in  = (k & 1) ? e1 : e0;
        float*       outp = (k & 1) ? e0 : e1;
        fused_layer_kernel<<<LBLK, 256>>>(in, outp,
                                          W_gc + k * D * D,
                                          W_bi + k * D * D,
                                          b_bi + k * D, k);
    }

    gather_kernel<<<(3 * B_SZ * 4 * D + 255) / 256, 256>>>(users, pos_items,
                                                           neg_items, out);
}